// round 12
// baseline (speedup 1.0000x reference)
#include <cuda_runtime.h>
#include <math.h>
#include <stdint.h>

#define NEURONS 54
#define NPAD    64
#define HN      27        // neurons per thread (half batch)
#define DT      4
#define STEPS   30
#define BATCHES 128
#define KDIM    5625      // 75*75
#define KPAD    5632      // 44*128
#define KC      128       // K chunk for FC
#define NKC     44        // 5632/128

// scratch (zero-initialized device globals)
__device__ float g_pooled[BATCHES * KPAD];          // [b][k]
__device__ float g_fcpart[NKC * BATCHES * NPAD];    // [kc][b][n]
__device__ float g_expxf[BATCHES * NEURONS];        // exp(xf)

// ---------------------------------------------------------------------------
// Kernel 1: pure streaming 8x8 avg-pool. One thread per pooled output,
// 16 independent evict-first LDG.128, no barriers, no smem.
// ---------------------------------------------------------------------------
__global__ void __launch_bounds__(256) pool_kernel(const float* __restrict__ x)
{
    int idx = blockIdx.x * 256 + threadIdx.x;
    if (idx < BATCHES * KDIM) {
        int b  = idx / KDIM;
        int r  = idx - b * KDIM;     // 0..5624
        int rg = r / 75;
        int p  = r - rg * 75;

        const float4* xp = (const float4*)x + ((b * 600 + rg * 8) * 150 + p * 2);
        float s = 0.f;
#pragma unroll
        for (int rr = 0; rr < 8; rr++) {
            float4 a = __ldcs(xp + rr * 150);
            float4 c = __ldcs(xp + rr * 150 + 1);
            s += (a.x + a.y) + (a.z + a.w) + (c.x + c.y) + (c.z + c.w);
        }
        g_pooled[b * KPAD + r] = s * (1.f / 64.f);
    }
    cudaTriggerProgrammaticLaunchCompletion();
}

// ---------------------------------------------------------------------------
// Kernel 2: split-K FC partials. grid = (44, 8 batch-tiles).
// PDL: stage Ws, trigger, then gridDepSync before reading g_pooled.
// ---------------------------------------------------------------------------
__global__ void __launch_bounds__(256) fc_kernel(const float* __restrict__ fc_w)
{
    __shared__ __align__(16) float Ws[NEURONS * KC];

    const int kc  = blockIdx.x;          // 0..43
    const int bt  = blockIdx.y;          // 0..7
    const int tid = threadIdx.x;
    const int k0  = kc * KC;

    for (int i = tid; i < NEURONS * KC; i += 256) {
        int n = i / KC, k = i - n * KC;
        int kg = k0 + k;
        Ws[i] = (kg < KDIM) ? fc_w[n * KDIM + kg] : 0.f;
    }
    cudaTriggerProgrammaticLaunchCompletion();
    __syncthreads();

    cudaGridDependencySynchronize();     // g_pooled ready beyond this point

    const int w = tid >> 5, lane = tid & 31;
    const int b0 = bt * 16 + w * 2;

    float4 p0 = ((const float4*)(g_pooled + (size_t)b0 * KPAD + k0))[lane];
    float4 p1 = ((const float4*)(g_pooled + (size_t)(b0 + 1) * KPAD + k0))[lane];
    const float4* W4 = (const float4*)Ws;

    for (int n = 0; n < NEURONS; n++) {
        float4 wv = W4[n * 32 + lane];
        float a0 = p0.x * wv.x + p0.y * wv.y + p0.z * wv.z + p0.w * wv.w;
        float a1 = p1.x * wv.x + p1.y * wv.y + p1.z * wv.z + p1.w * wv.w;
#pragma unroll
        for (int d = 16; d; d >>= 1) {
            a0 += __shfl_xor_sync(0xffffffffu, a0, d);
            a1 += __shfl_xor_sync(0xffffffffu, a1, d);
        }
        if (lane == 0) {
            g_fcpart[(kc * BATCHES + b0) * NPAD + n]     = a0;
            g_fcpart[(kc * BATCHES + b0 + 1) * NPAD + n] = a1;
        }
    }
}

// ---------------------------------------------------------------------------
// Kernel 3: reduce 44 K-partials, add bias, exponentiate -> g_expxf[b*54+n].
// grid=128, block=64. Parallel across SMs so the single-CTA glm doesn't have
// to chew 1.2MB itself.
// ---------------------------------------------------------------------------
__global__ void reduce_exp_kernel(const float* __restrict__ fc_b)
{
    cudaTriggerProgrammaticLaunchCompletion();
    cudaGridDependencySynchronize();     // g_fcpart ready

    const int b = blockIdx.x, n = threadIdx.x;
    float a = 0.f;
#pragma unroll 4
    for (int kc = 0; kc < NKC; kc++)
        a += g_fcpart[(kc * BATCHES + b) * NPAD + n];
    if (n < NEURONS)
        g_expxf[b * NEURONS + n] = expf(a + fc_b[n]);
}

// ---------------------------------------------------------------------------
// Kernel 4: 30-step GLM scan in ONE 256-thread CTA (no cross-SM sync!).
// Thread t: batch b = t/2, half h = t&1 -> neurons n0..n0+26 (n0 = 27h).
// Per step: 27x (nib extract + LDS.64 LUT + pe=exf*er, S+=hs, T+=pe) ->
// shfl d=1 combines halves -> eS=__expf(S_b) -> rs=eS*T_b -> butterfly over
// d={2,4,8,16} (even-offset closure: each of the warp's 16 batches summed
// exactly ONCE) -> lane0 STS -> ONE __syncthreads (double-buffered wp) ->
// 8-way sum = full 128-batch total -> thr = tot/(B*N) ->
// 27x spike compare (pe*eS>thr) + packed-nibble + packed-count update.
// ---------------------------------------------------------------------------
__global__ void __launch_bounds__(256, 1)
glm_kernel(const float* __restrict__ lw, const float* __restrict__ hw,
           float* __restrict__ out)
{
    __shared__ float2 lut[NEURONS * 18];      // {hs, exp(h-hs)}, pitch 18
    __shared__ __align__(16) float wp[2][8];  // [parity][warp]

    const int tid = threadIdx.x;
    const int lane = tid & 31, wid = tid >> 5;
    const int b  = tid >> 1;
    const int n0 = (tid & 1) * HN;

    // ---- independent prologue (overlaps producers via PDL) ----
    for (int e = tid; e < NEURONS * 16; e += 256) {
        int n = e >> 4, nib = e & 15;
        float hs = 0.f, hh = 0.f;
#pragma unroll
        for (int t = 0; t < DT; t++)
            if (nib & (1 << t)) { hs += lw[n * DT + t]; hh += hw[t]; }
        lut[n * 18 + nib] = make_float2(hs, expf(hh - hs));
    }

    cudaGridDependencySynchronize();     // g_expxf ready beyond this point

    float exf[HN];
#pragma unroll
    for (int i = 0; i < HN; i++) exf[i] = g_expxf[b * NEURONS + n0 + i];

    __syncthreads();                     // LUT visible

    unsigned pack[4] = {0u, 0u, 0u, 0u};     // 27 x 4-bit histories
    unsigned cntp[6] = {0u, 0u, 0u, 0u, 0u, 0u}; // 27 x 6-bit counters
    float pe[HN];

    for (int step = 0; step < STEPS; step++) {
        // compute phase: dual accumulators to break FADD chains
        float sv0 = 0.f, sv1 = 0.f, tv0 = 0.f, tv1 = 0.f;
#pragma unroll
        for (int i = 0; i < HN; i++) {
            unsigned nib = (pack[i >> 3] >> ((i & 7) * 4)) & 15u;
            float2 e = lut[(n0 + i) * 18 + nib];
            pe[i] = exf[i] * e.y;
            if (i & 1) { sv1 += e.x; tv1 += pe[i]; }
            else       { sv0 += e.x; tv0 += pe[i]; }
        }
        float sv = sv0 + sv1, tv = tv0 + tv1;

        // combine the two batch halves (adjacent lanes)
        sv += __shfl_xor_sync(0xffffffffu, sv, 1);
        tv += __shfl_xor_sync(0xffffffffu, tv, 1);
        const float eS = __expf(sv);
        float rs = eS * tv;              // batch rate-sum (dup across lane pair)
        rs += __shfl_xor_sync(0xffffffffu, rs, 2);
        rs += __shfl_xor_sync(0xffffffffu, rs, 4);
        rs += __shfl_xor_sync(0xffffffffu, rs, 8);
        rs += __shfl_xor_sync(0xffffffffu, rs, 16);
        // rs = sum over this warp's 16 distinct batches (each ONCE)

        const int par = step & 1;
        if (lane == 0) wp[par][wid] = rs;
        __syncthreads();

        const float4 A = *(const float4*)&wp[par][0];
        const float4 B = *(const float4*)&wp[par][4];
        const float tot = ((A.x + A.y) + (A.z + A.w)) + ((B.x + B.y) + (B.z + B.w));
        const float thr = tot * (1.0f / (BATCHES * NEURONS));

        // update phase: shift all nibbles, insert spike bits, bump counters
        unsigned np[4];
#pragma unroll
        for (int w2 = 0; w2 < 4; w2++) np[w2] = (pack[w2] >> 1) & 0x77777777u;
#pragma unroll
        for (int i = 0; i < HN; i++) {
            bool sp = pe[i] * eS > thr;      // proven spike formula
            if (sp) {
                np[i >> 3]  |= 8u << ((i & 7) * 4);
                cntp[i / 5] += 1u << (6 * (i % 5));
            }
        }
#pragma unroll
        for (int w2 = 0; w2 < 4; w2++) pack[w2] = np[w2];
    }

    // softplus(count), stable (count >= 0)
#pragma unroll
    for (int i = 0; i < HN; i++) {
        float c = (float)((cntp[i / 5] >> (6 * (i % 5))) & 63u);
        out[b * NEURONS + n0 + i] = c + log1pf(expf(-c));
    }
}

extern "C" void kernel_launch(void* const* d_in, const int* in_sizes, int n_in,
                              void* d_out, int out_size)
{
    const float* x   = (const float*)d_in[0];  // [128,1,600,600]
    const float* lw  = (const float*)d_in[1];  // [54,4]
    const float* hw  = (const float*)d_in[2];  // [4]
    const float* fcw = (const float*)d_in[3];  // [54,5625]
    const float* fcb = (const float*)d_in[4];  // [54]
    float* out = (float*)d_out;                // [128,54]

    pool_kernel<<<(BATCHES * KDIM + 255) / 256, 256>>>(x);

    cudaLaunchAttribute at[1];
    at[0].id = cudaLaunchAttributeProgrammaticStreamSerialization;
    at[0].val.programmaticStreamSerializationAllowed = 1;

    {   // fc: PDL-dependent on pool
        cudaLaunchConfig_t cfg = {};
        cfg.gridDim  = dim3(NKC, 8, 1);
        cfg.blockDim = dim3(256, 1, 1);
        cfg.attrs = at; cfg.numAttrs = 1; cfg.stream = 0;
        cudaLaunchKernelEx(&cfg, fc_kernel, fcw);
    }
    {   // reduce_exp: PDL-dependent on fc
        cudaLaunchConfig_t cfg = {};
        cfg.gridDim  = dim3(BATCHES, 1, 1);
        cfg.blockDim = dim3(NPAD, 1, 1);
        cfg.attrs = at; cfg.numAttrs = 1; cfg.stream = 0;
        cudaLaunchKernelEx(&cfg, reduce_exp_kernel, fcb);
    }
    {   // glm: PDL-dependent on reduce_exp
        cudaLaunchConfig_t cfg = {};
        cfg.gridDim  = dim3(1, 1, 1);
        cfg.blockDim = dim3(256, 1, 1);
        cfg.attrs = at; cfg.numAttrs = 1; cfg.stream = 0;
        cudaLaunchKernelEx(&cfg, glm_kernel, lw, hw, out);
    }
}